// round 2
// baseline (speedup 1.0000x reference)
#include <cuda_runtime.h>
#include <math.h>
#include <stddef.h>

// Problem constants
#define NN    4096      // nodes
#define TT    16        // timesteps / out features
#define FF    4         // node features
#define HIDC  64        // hidden per head
#define NH    4         // heads
#define NCHUNK 64
#define CHSZ   64       // NN / NCHUNK

// ---------------------------------------------------------------------------
// Scratch (static device global — no runtime allocation, accessed directly
// from kernels; kernel_launch performs kernel launches ONLY)
// ---------------------------------------------------------------------------
struct Scratch {
    // layer 1
    float  Wh[NH * NN * HIDC];        // per-head h@W
    float  s1[NH * NN];
    float  s2[NH * NN];
    float  s2s[NH * NN];              // sorted s2
    int    perm[NH * NN];             // sorted position -> original index
    float  A[NH * NN];                // exp(s2_sorted)
    float  B[NH * NN];                // exp(0.01*s2_sorted)
    double csA[NH * NCHUNK * HIDC];   // chunk sums -> exclusive suffix offsets
    double csB[NH * NCHUNK * HIDC];   // chunk sums -> exclusive prefix offsets
    float  sufA[NH * (NN + 1) * HIDC];
    float  preB[NH * (NN + 1) * HIDC];
    double sufAsc[NH * (NN + 1)];     // scalar suffix sums of A
    double preBsc[NH * (NN + 1)];     // scalar prefix sums of B
    float  hcat[NN * NH * HIDC];      // concatenated head outputs
    // layer 2
    float  Wh2[NN * TT];
    float  s1o[NN], s2o[NN], s2so[NN];
    int    permo[NN];
    float  Ao[NN], Bo[NN];
    double csA2[NCHUNK * TT], csB2[NCHUNK * TT];
    float  sufA2[(NN + 1) * TT], preB2[(NN + 1) * TT];
    double sufA2sc[NN + 1], preB2sc[NN + 1];
};
__device__ Scratch S;

// ---------------------------------------------------------------------------
// Kernel 1: fused transpose(x) -> h, Wh = h @ W[head], s1 = Wh@a1, s2 = Wh@a2
// grid (NN/64, NH), block 256
// ---------------------------------------------------------------------------
__global__ void k_gemm1(const float* __restrict__ x,
                        const float* __restrict__ W,
                        const float* __restrict__ a1,
                        const float* __restrict__ a2)
{
    __shared__ float sW[64 * 65];   // W during compute, reused for Wh tile
    __shared__ float sh[64 * 65];   // h tile (64 rows x 64 feats)

    const int head = blockIdx.y;
    const int n0   = blockIdx.x * 64;
    const int t    = threadIdx.x;

    // load W[head] (64x64, row-major [in][out])
    const float* Wp = W + head * 64 * 64;
    for (int idx = t; idx < 4096; idx += 256)
        sW[(idx >> 6) * 65 + (idx & 63)] = Wp[idx];

    // load h rows n0..n0+63: h[n][t16*4+f] = x[t16, n, f]
    {
        const int dn = t >> 2, f = t & 3;
        #pragma unroll
        for (int tt = 0; tt < TT; tt++)
            sh[dn * 65 + tt * 4 + f] = x[(size_t)tt * NN * FF + (size_t)(n0 + dn) * FF + f];
    }
    __syncthreads();

    const int tc = t & 15, tr = t >> 4;   // 16x16 threads, 4x4 register tile each
    float acc[4][4];
    #pragma unroll
    for (int i = 0; i < 4; i++)
        #pragma unroll
        for (int j = 0; j < 4; j++) acc[i][j] = 0.f;

    for (int k = 0; k < 64; k++) {
        float av[4], bv[4];
        #pragma unroll
        for (int i = 0; i < 4; i++) av[i] = sh[(tr + 16 * i) * 65 + k];
        #pragma unroll
        for (int j = 0; j < 4; j++) bv[j] = sW[k * 65 + tc + 16 * j];
        #pragma unroll
        for (int i = 0; i < 4; i++)
            #pragma unroll
            for (int j = 0; j < 4; j++) acc[i][j] = fmaf(av[i], bv[j], acc[i][j]);
    }
    __syncthreads();

    // write Wh to global and stash in smem (reuse sW) for s1/s2 dots
    #pragma unroll
    for (int i = 0; i < 4; i++) {
        const int r = tr + 16 * i;
        #pragma unroll
        for (int j = 0; j < 4; j++) {
            const int c = tc + 16 * j;
            sW[r * 65 + c] = acc[i][j];
            S.Wh[((size_t)head * NN + (n0 + r)) * HIDC + c] = acc[i][j];
        }
    }
    __syncthreads();

    if (t < 64) {
        const int r = t;
        const float* ap1 = a1 + head * HIDC;
        const float* ap2 = a2 + head * HIDC;
        float v1 = 0.f, v2 = 0.f;
        #pragma unroll
        for (int c = 0; c < 64; c++) {
            const float w = sW[r * 65 + c];
            v1 = fmaf(w, ap1[c], v1);
            v2 = fmaf(w, ap2[c], v2);
        }
        S.s1[head * NN + n0 + r] = v1;
        S.s2[head * NN + n0 + r] = v2;
    }
}

// ---------------------------------------------------------------------------
// Kernel 2: hcat @ W_out + s1o/s2o.  grid 256, block 256 (16 rows x 16 cols)
// ---------------------------------------------------------------------------
__global__ void k_gemm2(const float* __restrict__ Wo,
                        const float* __restrict__ a1,
                        const float* __restrict__ a2)
{
    __shared__ float sW[256 * 17];
    __shared__ float sh2[16 * 257];
    __shared__ float sAcc[16 * 17];

    const int row0 = blockIdx.x * 16;
    const int t    = threadIdx.x;

    for (int idx = t; idx < 4096; idx += 256)
        sW[(idx >> 4) * 17 + (idx & 15)] = Wo[idx];
    #pragma unroll
    for (int r = 0; r < 16; r++)
        sh2[r * 257 + t] = S.hcat[(size_t)(row0 + r) * 256 + t];
    __syncthreads();

    const int tc = t & 15, tr = t >> 4;
    float acc = 0.f;
    for (int k = 0; k < 256; k++)
        acc = fmaf(sh2[tr * 257 + k], sW[k * 17 + tc], acc);

    S.Wh2[(row0 + tr) * TT + tc] = acc;
    sAcc[tr * 17 + tc] = acc;
    __syncthreads();

    if (t < 16) {
        const int r = t;
        float v1 = 0.f, v2 = 0.f;
        #pragma unroll
        for (int c = 0; c < 16; c++) {
            const float w = sAcc[r * 17 + c];
            v1 = fmaf(w, a1[c], v1);
            v2 = fmaf(w, a2[c], v2);
        }
        S.s1o[row0 + r] = v1;
        S.s2o[row0 + r] = v2;
    }
}

// ---------------------------------------------------------------------------
// Kernel 3: bitonic sort of s2 (4096 elems) + exp weights.  block 1024, 1 blk/head
// ---------------------------------------------------------------------------
__global__ void k_sort(const float* __restrict__ s2,
                       float* __restrict__ s2s,
                       int* __restrict__ perm,
                       float* __restrict__ A,
                       float* __restrict__ B)
{
    __shared__ float key[NN];
    __shared__ int   sidx[NN];
    const int base = blockIdx.x * NN;
    const int t = threadIdx.x;

    #pragma unroll
    for (int m = 0; m < 4; m++) {
        const int i = t + m * 1024;
        key[i] = s2[base + i];
        sidx[i] = i;
    }
    __syncthreads();

    for (int k = 2; k <= NN; k <<= 1) {
        for (int j = k >> 1; j > 0; j >>= 1) {
            #pragma unroll
            for (int m = 0; m < 4; m++) {
                const int i = t + m * 1024;
                const int ixj = i ^ j;
                if (ixj > i) {
                    const bool up = ((i & k) == 0);
                    const float a = key[i], b = key[ixj];
                    if ((a > b) == up) {
                        key[i] = b; key[ixj] = a;
                        const int tmp = sidx[i]; sidx[i] = sidx[ixj]; sidx[ixj] = tmp;
                    }
                }
            }
            __syncthreads();
        }
    }

    #pragma unroll
    for (int m = 0; m < 4; m++) {
        const int i = t + m * 1024;
        const float v = key[i];
        s2s[base + i]  = v;
        perm[base + i] = sidx[i];
        A[base + i]    = expf(v);
        B[base + i]    = expf(0.01f * v);
    }
}

// ---------------------------------------------------------------------------
// Kernel 4: per-chunk fp64 column sums of A*Wh[perm] and B*Wh[perm]
// ---------------------------------------------------------------------------
template<int C, int CPB>
__global__ void k_chunksum(const float* __restrict__ Wh,
                           const int* __restrict__ perm,
                           const float* __restrict__ A,
                           const float* __restrict__ B,
                           double* __restrict__ csA,
                           double* __restrict__ csB)
{
    const int head = blockIdx.x;
    Wh   += (size_t)head * NN * C;
    perm += head * NN;
    A    += head * NN;
    B    += head * NN;
    csA  += head * NCHUNK * C;
    csB  += head * NCHUNK * C;

    const int c = threadIdx.x % C;
    const int q = blockIdx.y * CPB + threadIdx.x / C;
    const int p0 = q * CHSZ;
    double sa = 0.0, sb = 0.0;
    for (int e = 0; e < CHSZ; e++) {
        const int p = p0 + e;
        const float w = Wh[(size_t)perm[p] * C + c];
        sa += (double)A[p] * w;
        sb += (double)B[p] * w;
    }
    csA[q * C + c] = sa;
    csB[q * C + c] = sb;
}

// Kernel 5: scan chunk sums -> exclusive prefix (B) / exclusive suffix (A) offsets
template<int C>
__global__ void k_chunkscan(double* __restrict__ csA, double* __restrict__ csB)
{
    const int head = blockIdx.x;
    csA += head * NCHUNK * C;
    csB += head * NCHUNK * C;
    const int c = threadIdx.x;

    double run = 0.0;
    for (int q = 0; q < NCHUNK; q++) {
        const double v = csB[q * C + c];
        csB[q * C + c] = run;
        run += v;
    }
    run = 0.0;
    for (int q = NCHUNK - 1; q >= 0; q--) {
        const double v = csA[q * C + c];
        csA[q * C + c] = run;
        run += v;
    }
}

// Kernel 6: write full-resolution prefix/suffix arrays
template<int C, int CPB>
__global__ void k_pass3(const float* __restrict__ Wh,
                        const int* __restrict__ perm,
                        const float* __restrict__ A,
                        const float* __restrict__ B,
                        const double* __restrict__ csA,
                        const double* __restrict__ csB,
                        float* __restrict__ sufA,
                        float* __restrict__ preB)
{
    const int head = blockIdx.x;
    Wh   += (size_t)head * NN * C;
    perm += head * NN;
    A    += head * NN;
    B    += head * NN;
    csA  += head * NCHUNK * C;
    csB  += head * NCHUNK * C;
    sufA += (size_t)head * (NN + 1) * C;
    preB += (size_t)head * (NN + 1) * C;

    const int c = threadIdx.x % C;
    const int q = blockIdx.y * CPB + threadIdx.x / C;
    const int p0 = q * CHSZ;

    double run = csB[q * C + c];
    for (int e = 0; e < CHSZ; e++) {
        const int p = p0 + e;
        preB[(size_t)p * C + c] = (float)run;
        run += (double)B[p] * Wh[(size_t)perm[p] * C + c];
    }
    if (q == NCHUNK - 1) preB[(size_t)NN * C + c] = (float)run;

    run = csA[q * C + c];
    if (q == NCHUNK - 1) sufA[(size_t)NN * C + c] = 0.f;
    for (int e = CHSZ - 1; e >= 0; e--) {
        const int p = p0 + e;
        run += (double)A[p] * Wh[(size_t)perm[p] * C + c];
        sufA[(size_t)p * C + c] = (float)run;
    }
}

// Kernel 7: scalar prefix(B)/suffix(A) sums in fp64.  block 256, 1 blk/head
__global__ void k_scalarscan(const float* __restrict__ A,
                             const float* __restrict__ B,
                             double* __restrict__ sufAsc,
                             double* __restrict__ preBsc)
{
    __shared__ double segA[256], segB[256];
    __shared__ double totA, totB;
    const int head = blockIdx.x;
    A      += head * NN;
    B      += head * NN;
    sufAsc += head * (NN + 1);
    preBsc += head * (NN + 1);

    const int t = threadIdx.x;
    const int base = t * 16;
    double la = 0.0, lb = 0.0;
    #pragma unroll
    for (int e = 0; e < 16; e++) { la += A[base + e]; lb += B[base + e]; }
    segA[t] = la; segB[t] = lb;
    __syncthreads();

    if (t == 0) {
        double ra = 0.0, rb = 0.0;
        for (int s = 0; s < 256; s++) {
            const double ta = segA[s]; segA[s] = ra; ra += ta;
            const double tb = segB[s]; segB[s] = rb; rb += tb;
        }
        totA = ra; totB = rb;
    }
    __syncthreads();

    double runB = segB[t];
    double preA = segA[t];
    const double tA = totA;
    #pragma unroll
    for (int e = 0; e < 16; e++) {
        const int p = base + e;
        preBsc[p] = runB;      runB += B[p];
        sufAsc[p] = tA - preA; preA += A[p];
    }
    if (t == 255) { preBsc[NN] = runB; sufAsc[NN] = 0.0; }
}

// ---------------------------------------------------------------------------
// Kernel 8: per-row combine: binary search split point, assemble numer/denom,
// subtract diagonal, optional ELU.  block 256 = (256/C) rows x C channels.
// ---------------------------------------------------------------------------
template<int C, bool DO_ELU>
__global__ void k_combine(const float* __restrict__ s1,
                          const float* __restrict__ s2,
                          const float* __restrict__ s2s,
                          const float* __restrict__ Wh,
                          const float* __restrict__ sufA,
                          const float* __restrict__ preB,
                          const double* __restrict__ sufAsc,
                          const double* __restrict__ preBsc,
                          float* __restrict__ out,
                          int rowStride)
{
    const int head = blockIdx.y;
    s1     += head * NN;
    s2     += head * NN;
    s2s    += head * NN;
    Wh     += (size_t)head * NN * C;
    sufA   += (size_t)head * (NN + 1) * C;
    preB   += (size_t)head * (NN + 1) * C;
    sufAsc += head * (NN + 1);
    preBsc += head * (NN + 1);

    constexpr int IPB = 256 / C;
    const int i = blockIdx.x * IPB + threadIdx.x / C;
    const int c = threadIdx.x % C;

    const float s1v = s1[i];
    const float ea  = expf(s1v);
    const float eb  = expf(0.01f * s1v);

    // lower_bound(s2s, -s1v): first p with s2s[p] >= -s1v
    const float target = -s1v;
    int lo = 0, hi = NN;
    while (lo < hi) {
        const int mid = (lo + hi) >> 1;
        if (s2s[mid] < target) lo = mid + 1; else hi = mid;
    }
    const int k = lo;

    const float tii = s1v + s2[i];
    const float wii = expf(tii >= 0.f ? tii : 0.01f * tii);

    const double denom = (double)ea * sufAsc[k] + (double)eb * preBsc[k] - (double)wii;
    const float num = ea * sufA[(size_t)k * C + c]
                    + eb * preB[(size_t)k * C + c]
                    - wii * Wh[(size_t)i * C + c];
    float v = (float)((double)num / denom);
    if (DO_ELU) v = (v > 0.f) ? v : expm1f(v);

    out[(size_t)i * rowStride + head * C + c] = v;
}

// helper kernels need raw pointers into S; take them via device-side symbol
// references bound at launch using plain device pointers derived on host is
// disallowed-free; instead we use small wrapper kernels? Simpler: pass
// nothing — kernels above already take pointers; we obtain them via
// __device__ globals' addresses, which the compiler resolves per-kernel when
// referenced directly. To keep the generic templates, we add thin wrappers.

__global__ void k_sort1_wrap() {}  // (unused placeholder removed below)

// ---------------------------------------------------------------------------
// launch — kernel launches ONLY; scratch addresses resolved via device lambdas
// ---------------------------------------------------------------------------

// Thin launchers that bind template kernels to S's members from device code
// would complicate things; instead note that taking the address of a
// __device__ variable in HOST code is invalid, but passing sub-pointers is
// needed. Solution: a tiny setup kernel publishes pointers into a device
// pointer table that subsequent kernels read... that adds a launch. Simplest
// legal approach: kernels index into S directly via constexpr offsets.
// The template kernels above take pointers; we wrap them:

template<int C, int CPB, int L>   // L: 0 = layer1, 1 = layer2
__global__ void k_chunksum_w()
{
    const float*  Wh   = (L == 0) ? S.Wh   : S.Wh2;
    const int*    perm = (L == 0) ? S.perm : S.permo;
    const float*  A    = (L == 0) ? S.A    : S.Ao;
    const float*  B    = (L == 0) ? S.B    : S.Bo;
    double*       csA  = (L == 0) ? S.csA  : S.csA2;
    double*       csB  = (L == 0) ? S.csB  : S.csB2;

    const int head = blockIdx.x;
    Wh   += (size_t)head * NN * C;  perm += head * NN;
    A    += head * NN;              B    += head * NN;
    csA  += head * NCHUNK * C;      csB  += head * NCHUNK * C;

    const int c = threadIdx.x % C;
    const int q = blockIdx.y * CPB + threadIdx.x / C;
    const int p0 = q * CHSZ;
    double sa = 0.0, sb = 0.0;
    for (int e = 0; e < CHSZ; e++) {
        const int p = p0 + e;
        const float w = Wh[(size_t)perm[p] * C + c];
        sa += (double)A[p] * w;
        sb += (double)B[p] * w;
    }
    csA[q * C + c] = sa;
    csB[q * C + c] = sb;
}

template<int C, int L>
__global__ void k_chunkscan_w()
{
    double* csA = (L == 0) ? S.csA : S.csA2;
    double* csB = (L == 0) ? S.csB : S.csB2;
    const int head = blockIdx.x;
    csA += head * NCHUNK * C;
    csB += head * NCHUNK * C;
    const int c = threadIdx.x;

    double run = 0.0;
    for (int q = 0; q < NCHUNK; q++) {
        const double v = csB[q * C + c];
        csB[q * C + c] = run;
        run += v;
    }
    run = 0.0;
    for (int q = NCHUNK - 1; q >= 0; q--) {
        const double v = csA[q * C + c];
        csA[q * C + c] = run;
        run += v;
    }
}

template<int C, int CPB, int L>
__global__ void k_pass3_w()
{
    const float*  Wh   = (L == 0) ? S.Wh   : S.Wh2;
    const int*    perm = (L == 0) ? S.perm : S.permo;
    const float*  A    = (L == 0) ? S.A    : S.Ao;
    const float*  B    = (L == 0) ? S.B    : S.Bo;
    const double* csA  = (L == 0) ? S.csA  : S.csA2;
    const double* csB  = (L == 0) ? S.csB  : S.csB2;
    float*        sufA = (L == 0) ? S.sufA : S.sufA2;
    float*        preB = (L == 0) ? S.preB : S.preB2;

    const int head = blockIdx.x;
    Wh   += (size_t)head * NN * C;        perm += head * NN;
    A    += head * NN;                    B    += head * NN;
    csA  += head * NCHUNK * C;            csB  += head * NCHUNK * C;
    sufA += (size_t)head * (NN + 1) * C;  preB += (size_t)head * (NN + 1) * C;

    const int c = threadIdx.x % C;
    const int q = blockIdx.y * CPB + threadIdx.x / C;
    const int p0 = q * CHSZ;

    double run = csB[q * C + c];
    for (int e = 0; e < CHSZ; e++) {
        const int p = p0 + e;
        preB[(size_t)p * C + c] = (float)run;
        run += (double)B[p] * Wh[(size_t)perm[p] * C + c];
    }
    if (q == NCHUNK - 1) preB[(size_t)NN * C + c] = (float)run;

    run = csA[q * C + c];
    if (q == NCHUNK - 1) sufA[(size_t)NN * C + c] = 0.f;
    for (int e = CHSZ - 1; e >= 0; e--) {
        const int p = p0 + e;
        run += (double)A[p] * Wh[(size_t)perm[p] * C + c];
        sufA[(size_t)p * C + c] = (float)run;
    }
}

template<int L>
__global__ void k_sort_w()
{
    const float* s2  = (L == 0) ? S.s2  : S.s2o;
    float*       s2s = (L == 0) ? S.s2s : S.s2so;
    int*         perm= (L == 0) ? S.perm: S.permo;
    float*       A   = (L == 0) ? S.A   : S.Ao;
    float*       B   = (L == 0) ? S.B   : S.Bo;

    __shared__ float key[NN];
    __shared__ int   sidx[NN];
    const int base = blockIdx.x * NN;
    const int t = threadIdx.x;

    #pragma unroll
    for (int m = 0; m < 4; m++) {
        const int i = t + m * 1024;
        key[i] = s2[base + i];
        sidx[i] = i;
    }
    __syncthreads();

    for (int k = 2; k <= NN; k <<= 1) {
        for (int j = k >> 1; j > 0; j >>= 1) {
            #pragma unroll
            for (int m = 0; m < 4; m++) {
                const int i = t + m * 1024;
                const int ixj = i ^ j;
                if (ixj > i) {
                    const bool up = ((i & k) == 0);
                    const float a = key[i], b = key[ixj];
                    if ((a > b) == up) {
                        key[i] = b; key[ixj] = a;
                        const int tmp = sidx[i]; sidx[i] = sidx[ixj]; sidx[ixj] = tmp;
                    }
                }
            }
            __syncthreads();
        }
    }

    #pragma unroll
    for (int m = 0; m < 4; m++) {
        const int i = t + m * 1024;
        const float v = key[i];
        s2s[base + i]  = v;
        perm[base + i] = sidx[i];
        A[base + i]    = expf(v);
        B[base + i]    = expf(0.01f * v);
    }
}

template<int L>
__global__ void k_scalarscan_w()
{
    const float* A      = (L == 0) ? S.A      : S.Ao;
    const float* B      = (L == 0) ? S.B      : S.Bo;
    double*      sufAsc = (L == 0) ? S.sufAsc : S.sufA2sc;
    double*      preBsc = (L == 0) ? S.preBsc : S.preB2sc;

    __shared__ double segA[256], segB[256];
    __shared__ double totA, totB;
    const int head = blockIdx.x;
    A      += head * NN;
    B      += head * NN;
    sufAsc += head * (NN + 1);
    preBsc += head * (NN + 1);

    const int t = threadIdx.x;
    const int base = t * 16;
    double la = 0.0, lb = 0.0;
    #pragma unroll
    for (int e = 0; e < 16; e++) { la += A[base + e]; lb += B[base + e]; }
    segA[t] = la; segB[t] = lb;
    __syncthreads();

    if (t == 0) {
        double ra = 0.0, rb = 0.0;
        for (int s = 0; s < 256; s++) {
            const double ta = segA[s]; segA[s] = ra; ra += ta;
            const double tb = segB[s]; segB[s] = rb; rb += tb;
        }
        totA = ra; totB = rb;
    }
    __syncthreads();

    double runB = segB[t];
    double preA = segA[t];
    const double tA = totA;
    #pragma unroll
    for (int e = 0; e < 16; e++) {
        const int p = base + e;
        preBsc[p] = runB;      runB += B[p];
        sufAsc[p] = tA - preA; preA += A[p];
    }
    if (t == 255) { preBsc[NN] = runB; sufAsc[NN] = 0.0; }
}

template<int C, bool DO_ELU, int L>
__global__ void k_combine_w(float* __restrict__ extOut, int rowStride)
{
    const float*  s1     = (L == 0) ? S.s1     : S.s1o;
    const float*  s2     = (L == 0) ? S.s2     : S.s2o;
    const float*  s2s    = (L == 0) ? S.s2s    : S.s2so;
    const float*  Wh     = (L == 0) ? S.Wh     : S.Wh2;
    const float*  sufA   = (L == 0) ? S.sufA   : S.sufA2;
    const float*  preB   = (L == 0) ? S.preB   : S.preB2;
    const double* sufAsc = (L == 0) ? S.sufAsc : S.sufA2sc;
    const double* preBsc = (L == 0) ? S.preBsc : S.preB2sc;
    float* out = (L == 0) ? S.hcat : extOut;

    const int head = blockIdx.y;
    s1     += head * NN;
    s2     += head * NN;
    s2s    += head * NN;
    Wh     += (size_t)head * NN * C;
    sufA   += (size_t)head * (NN + 1) * C;
    preB   += (size_t)head * (NN + 1) * C;
    sufAsc += head * (NN + 1);
    preBsc += head * (NN + 1);

    constexpr int IPB = 256 / C;
    const int i = blockIdx.x * IPB + threadIdx.x / C;
    const int c = threadIdx.x % C;

    const float s1v = s1[i];
    const float ea  = expf(s1v);
    const float eb  = expf(0.01f * s1v);

    const float target = -s1v;
    int lo = 0, hi = NN;
    while (lo < hi) {
        const int mid = (lo + hi) >> 1;
        if (s2s[mid] < target) lo = mid + 1; else hi = mid;
    }
    const int k = lo;

    const float tii = s1v + s2[i];
    const float wii = expf(tii >= 0.f ? tii : 0.01f * tii);

    const double denom = (double)ea * sufAsc[k] + (double)eb * preBsc[k] - (double)wii;
    const float num = ea * sufA[(size_t)k * C + c]
                    + eb * preB[(size_t)k * C + c]
                    - wii * Wh[(size_t)i * C + c];
    float v = (float)((double)num / denom);
    if (DO_ELU) v = (v > 0.f) ? v : expm1f(v);

    out[(size_t)i * rowStride + head * C + c] = v;
}

extern "C" void kernel_launch(void* const* d_in, const int* in_sizes, int n_in,
                              void* d_out, int out_size)
{
    const float* x       = (const float*)d_in[0];
    const float* W_heads = (const float*)d_in[3];
    const float* a1h     = (const float*)d_in[4];
    const float* a2h     = (const float*)d_in[5];
    const float* W_out   = (const float*)d_in[6];
    const float* a1o     = (const float*)d_in[7];
    const float* a2o     = (const float*)d_in[8];
    float* out = (float*)d_out;

    // ---- layer 1 (4 heads) ----
    k_gemm1<<<dim3(NN / 64, NH), 256>>>(x, W_heads, a1h, a2h);
    k_sort_w<0><<<NH, 1024>>>();
    k_chunksum_w<HIDC, 4, 0><<<dim3(NH, NCHUNK / 4), 256>>>();
    k_chunkscan_w<HIDC, 0><<<NH, HIDC>>>();
    k_pass3_w<HIDC, 4, 0><<<dim3(NH, NCHUNK / 4), 256>>>();
    k_scalarscan_w<0><<<NH, 256>>>();
    k_combine_w<HIDC, true, 0><<<dim3(NN / 4, NH), 256>>>(nullptr, NH * HIDC);

    // ---- layer 2 (output) ----
    k_gemm2<<<NN / 16, 256>>>(W_out, a1o, a2o);
    k_sort_w<1><<<1, 1024>>>();
    k_chunksum_w<TT, 16, 1><<<dim3(1, NCHUNK / 16), 256>>>();
    k_chunkscan_w<TT, 1><<<1, TT>>>();
    k_pass3_w<TT, 16, 1><<<dim3(1, NCHUNK / 16), 256>>>();
    k_scalarscan_w<1><<<1, 256>>>();
    k_combine_w<TT, false, 1><<<dim3(NN / 16, 1), 256>>>(out, TT);
}